// round 1
// baseline (speedup 1.0000x reference)
#include <cuda_runtime.h>

#define SQ 2048
#define DH 64
#define NH 16
#define NB 4
#define QT 128   // q rows per CTA
#define KT 64    // k cols per tile
#define NT 256   // threads per CTA
#define OUT_ELEMS (NB*NH*SQ*DH)   // 8388608 floats: out tensor, attn follows

// Dynamic smem layout (two phases alias the same buffer):
//  Phase 1: Qst[64][132] (Q^T, scaled)  + Kst[64][68] (K^T)   = 51200 B
//  Phase 2: Vs [64][64]                 + Ps [128][64]        = 49152 B
#define SMEM_BYTES 51200

__global__ __launch_bounds__(NT, 2)
void sdpa_fused_kernel(const float* __restrict__ qg,
                       const float* __restrict__ kg,
                       const float* __restrict__ vg,
                       const int*   __restrict__ maskg,
                       float* __restrict__ outg)
{
    extern __shared__ float smem[];
    float (*Qst)[QT+4] = reinterpret_cast<float (*)[QT+4]>(smem);             // [d][i]
    float (*Kst)[KT+4] = reinterpret_cast<float (*)[KT+4]>(smem + DH*(QT+4)); // [d][j]
    float (*Vs)[DH]    = reinterpret_cast<float (*)[DH]>(smem);               // [j][d]
    float (*Ps)[KT]    = reinterpret_cast<float (*)[KT]>(smem + KT*DH);       // [i][j]

    const int h   = blockIdx.x;
    const int qt  = blockIdx.y;
    const int b   = blockIdx.z;
    const int tid = threadIdx.x;
    const int ty  = tid >> 4;   // 0..15 -> 8-row group
    const int tx  = tid & 15;   // 0..15 -> 4-col group
    const int q0  = qt * QT;

    const size_t bh = (size_t)(b*NH + h);
    const float* qb = qg + (bh*SQ + (size_t)q0)*DH;
    const float* kb = kg + bh*SQ*DH;
    const float* vb = vg + bh*SQ*DH;
    const int*   mb = maskg + ((size_t)b*SQ + (size_t)q0)*SQ;
    float* attn = outg + (size_t)OUT_ELEMS + (bh*SQ + (size_t)q0)*SQ;
    float* outb = outg + (bh*SQ + (size_t)q0)*DH;

    // ---- load Q tile transposed into smem, folding in the 1/sqrt(64) scale ----
    for (int idx = tid; idx < QT*DH; idx += NT) {
        int i = idx >> 6, d = idx & 63;
        Qst[d][i] = qb[i*DH + d] * 0.125f;
    }

    float m[8], l[8];
#pragma unroll
    for (int ii = 0; ii < 8; ii++) { m[ii] = -1e30f; l[ii] = 0.0f; }

    // ================= PASS 1: scores + mask + online (max,sum); stash raw s in attn =================
    for (int kt0 = 0; kt0 < SQ; kt0 += KT) {
        __syncthreads();
        for (int idx = tid; idx < KT*DH; idx += NT) {
            int j = idx >> 6, d = idx & 63;
            Kst[d][j] = kb[(kt0 + j)*DH + d];
        }
        __syncthreads();

        float s[8][4];
#pragma unroll
        for (int ii = 0; ii < 8; ii++)
#pragma unroll
            for (int jj = 0; jj < 4; jj++) s[ii][jj] = 0.0f;

#pragma unroll 16
        for (int d = 0; d < DH; d++) {
            float4 k4 = *reinterpret_cast<const float4*>(&Kst[d][tx*4]);
            float4 qa = *reinterpret_cast<const float4*>(&Qst[d][ty*8]);
            float4 qc = *reinterpret_cast<const float4*>(&Qst[d][ty*8 + 4]);
            float qr[8] = {qa.x, qa.y, qa.z, qa.w, qc.x, qc.y, qc.z, qc.w};
#pragma unroll
            for (int ii = 0; ii < 8; ii++) {
                s[ii][0] += qr[ii]*k4.x;
                s[ii][1] += qr[ii]*k4.y;
                s[ii][2] += qr[ii]*k4.z;
                s[ii][3] += qr[ii]*k4.w;
            }
        }

#pragma unroll
        for (int ii = 0; ii < 8; ii++) {
            int row = ty*8 + ii;
            int4 mk = *reinterpret_cast<const int4*>(&mb[(size_t)row*SQ + kt0 + tx*4]);
            if (mk.x == 0) s[ii][0] = -1e9f;
            if (mk.y == 0) s[ii][1] = -1e9f;
            if (mk.z == 0) s[ii][2] = -1e9f;
            if (mk.w == 0) s[ii][3] = -1e9f;
            *reinterpret_cast<float4*>(&attn[(size_t)row*SQ + kt0 + tx*4]) =
                make_float4(s[ii][0], s[ii][1], s[ii][2], s[ii][3]);

            // row max over this 64-wide tile (16 tx lanes hold the row)
            float tmax = fmaxf(fmaxf(s[ii][0], s[ii][1]), fmaxf(s[ii][2], s[ii][3]));
            tmax = fmaxf(tmax, __shfl_xor_sync(0xffffffffu, tmax, 8));
            tmax = fmaxf(tmax, __shfl_xor_sync(0xffffffffu, tmax, 4));
            tmax = fmaxf(tmax, __shfl_xor_sync(0xffffffffu, tmax, 2));
            tmax = fmaxf(tmax, __shfl_xor_sync(0xffffffffu, tmax, 1));
            float mn = fmaxf(m[ii], tmax);

            float e0 = (s[ii][0] > -1e8f) ? __expf(s[ii][0] - mn) : 0.0f;
            float e1 = (s[ii][1] > -1e8f) ? __expf(s[ii][1] - mn) : 0.0f;
            float e2 = (s[ii][2] > -1e8f) ? __expf(s[ii][2] - mn) : 0.0f;
            float e3 = (s[ii][3] > -1e8f) ? __expf(s[ii][3] - mn) : 0.0f;
            float ts = (e0 + e1) + (e2 + e3);
            ts += __shfl_xor_sync(0xffffffffu, ts, 8);
            ts += __shfl_xor_sync(0xffffffffu, ts, 4);
            ts += __shfl_xor_sync(0xffffffffu, ts, 2);
            ts += __shfl_xor_sync(0xffffffffu, ts, 1);

            l[ii] = l[ii]*__expf(m[ii] - mn) + ts;
            m[ii] = mn;
        }
    }

    float invl[8];
#pragma unroll
    for (int ii = 0; ii < 8; ii++) invl[ii] = 1.0f / l[ii];

    float o[8][4];
#pragma unroll
    for (int ii = 0; ii < 8; ii++)
#pragma unroll
        for (int jj = 0; jj < 4; jj++) o[ii][jj] = 0.0f;

    // ================= PASS 2: p = exp(s-m)/l, write attn, O += P*V =================
    for (int kt0 = 0; kt0 < SQ; kt0 += KT) {
        __syncthreads();
        for (int idx = tid; idx < KT*DH/4; idx += NT) {
            int j = idx >> 4, dq = idx & 15;
            reinterpret_cast<float4*>(Vs[j])[dq] =
                reinterpret_cast<const float4*>(&vb[(kt0 + j)*DH])[dq];
        }
#pragma unroll
        for (int ii = 0; ii < 8; ii++) {
            int row = ty*8 + ii;
            float4 sv = *reinterpret_cast<const float4*>(&attn[(size_t)row*SQ + kt0 + tx*4]);
            float4 pv;
            pv.x = (sv.x > -1e8f) ? __expf(sv.x - m[ii]) * invl[ii] : 0.0f;
            pv.y = (sv.y > -1e8f) ? __expf(sv.y - m[ii]) * invl[ii] : 0.0f;
            pv.z = (sv.z > -1e8f) ? __expf(sv.z - m[ii]) * invl[ii] : 0.0f;
            pv.w = (sv.w > -1e8f) ? __expf(sv.w - m[ii]) * invl[ii] : 0.0f;
            *reinterpret_cast<float4*>(&attn[(size_t)row*SQ + kt0 + tx*4]) = pv;
            *reinterpret_cast<float4*>(&Ps[row][tx*4]) = pv;
        }
        __syncthreads();

#pragma unroll 8
        for (int j = 0; j < KT; j++) {
            float4 vv = *reinterpret_cast<const float4*>(&Vs[j][tx*4]);
#pragma unroll
            for (int ii = 0; ii < 8; ii++) {
                float p = Ps[ty*8 + ii][j];
                o[ii][0] += p*vv.x;
                o[ii][1] += p*vv.y;
                o[ii][2] += p*vv.z;
                o[ii][3] += p*vv.w;
            }
        }
    }

#pragma unroll
    for (int ii = 0; ii < 8; ii++) {
        *reinterpret_cast<float4*>(&outb[(ty*8 + ii)*DH + tx*4]) =
            make_float4(o[ii][0], o[ii][1], o[ii][2], o[ii][3]);
    }
}

extern "C" void kernel_launch(void* const* d_in, const int* in_sizes, int n_in,
                              void* d_out, int out_size) {
    const float* q   = (const float*)d_in[0];
    const float* k   = (const float*)d_in[1];
    const float* v   = (const float*)d_in[2];
    const int*   msk = (const int*)d_in[3];
    float* out = (float*)d_out;

    cudaFuncSetAttribute(sdpa_fused_kernel,
                         cudaFuncAttributeMaxDynamicSharedMemorySize, SMEM_BYTES);

    dim3 grid(NH, SQ/QT, NB);   // h fastest: mask rows reused across heads in L2
    sdpa_fused_kernel<<<grid, NT, SMEM_BYTES>>>(q, k, v, msk, out);
}